// round 6
// baseline (speedup 1.0000x reference)
#include <cuda_runtime.h>
#include <cstdint>

// ---------------------------------------------------------------------------
// TT embedding:  VOC = 100^3,  EMB = 4*4*8 = 128,  RANK = 16
//   out[tok, n1*32+n2*8+n3] = sum_{r1,r2} core0[i1,n1,r1]*core1[r1,i2,n2,r2]*core2[r2,i3,n3]
// idx = i1*10000 + i2*100 + i3; idx==0 (PAD) -> zero row.
//
// Kernel 1 : G01[i12][row*16+r2] = sum_r1 core0*core1  (10.2MB, L2-resident)
// Kernel 1b: C2Q[i3][rp][n3][s]  = core2[2rp+s][i3][n3] (51KB, r2-pairs packed)
// Kernel 2 : warp/token (R2 structure), FFMA2 over r2-PAIRS: both operands
//            come straight from loads -> no broadcast MOVs, depth-8 chains.
// ---------------------------------------------------------------------------

#define VOC_LL 1000000ULL

__device__ float g_G01[10000 * 256];
__device__ float g_C2Q[100 * 128];     // [i3][rp][n3][s] : s = r2 parity

// ---- packed fp32x2 helpers (sm_103a) --------------------------------------
__device__ __forceinline__ unsigned long long f32x2_fma(
    unsigned long long a, unsigned long long b, unsigned long long c)
{
    unsigned long long d;
    asm("fma.rn.f32x2 %0, %1, %2, %3;" : "=l"(d) : "l"(a), "l"(b), "l"(c));
    return d;
}
__device__ __forceinline__ unsigned long long f32x2_bcast(float x)
{
    unsigned long long d;
    asm("mov.b64 %0, {%1, %1};" : "=l"(d) : "f"(x));
    return d;
}
__device__ __forceinline__ float f32x2_hadd(unsigned long long v)
{
    float lo, hi;
    asm("mov.b64 {%0, %1}, %2;" : "=f"(lo), "=f"(hi) : "l"(v));
    return lo + hi;
}

// ---------------------------------------------------------------------------
// Kernel 1: G01 precompute.  grid=(100 [i2], 20 [i1-group of 5]), block=128.
// core0: (1,100,4,16)  elem (i1,n1,r1)    @ i1*64 + n1*16 + r1
// core1: (16,100,4,16) elem (r1,i2,n2,r2) @ r1*6400 + i2*64 + n2*16 + r2
// ---------------------------------------------------------------------------
__global__ void __launch_bounds__(128) tt_precompute_g01(
    const float* __restrict__ core0,
    const float* __restrict__ core1)
{
    __shared__ float Bs[1024];   // core1 slice for this i2: [r1][n2*16+r2]
    __shared__ float As[320];    // core0 slices for 5 i1: [q][n1*16+r1]

    const int i2 = blockIdx.x;
    const int g  = blockIdx.y;   // i1 in [5g, 5g+5)
    const int p  = threadIdx.x;

    #pragma unroll
    for (int j = p; j < 1024; j += 128)
        Bs[j] = core1[(j >> 6) * 6400 + i2 * 64 + (j & 63)];
    #pragma unroll
    for (int j = p; j < 320; j += 128)
        As[j] = core0[g * 320 + j];
    __syncthreads();

    const int n1 = p >> 5;         // constant per warp -> As broadcast
    const int rp = (p & 31) * 2;   // rest pair start (n2*16+r2)

    unsigned long long b2[16];
    #pragma unroll
    for (int r1 = 0; r1 < 16; r1++)
        b2[r1] = *(const unsigned long long*)&Bs[r1 * 64 + rp];

    #pragma unroll
    for (int q = 0; q < 5; q++) {
        unsigned long long acc = 0;
        #pragma unroll
        for (int r1 = 0; r1 < 16; r1++)
            acc = f32x2_fma(f32x2_bcast(As[q * 64 + n1 * 16 + r1]), b2[r1], acc);
        const int i1 = g * 5 + q;
        *(unsigned long long*)&g_G01[((size_t)(i1 * 100 + i2)) * 256 + p * 2] = acc;
    }
}

// ---------------------------------------------------------------------------
// Kernel 1b: core2 transpose into r2-pair-packed layout.
// core2: (16,100,8) elem (r2,i3,n3) @ r2*800 + i3*8 + n3
// C2Q  : float idx = i3*128 + rp*16 + n3*2 + s  ==  core2[(2rp+s)*800+i3*8+n3]
// ---------------------------------------------------------------------------
__global__ void __launch_bounds__(256) tt_pack_c2(const float* __restrict__ core2)
{
    const int o = blockIdx.x * 256 + threadIdx.x;
    if (o >= 100 * 128) return;
    const int i3 = o >> 7;
    const int rm = o & 127;
    const int rp = rm >> 4;
    const int n3 = (rm >> 1) & 7;
    const int s  = rm & 1;
    g_C2Q[o] = core2[(2 * rp + s) * 800 + i3 * 8 + n3];
}

// ---------------------------------------------------------------------------
// Kernel 2: gather.  1 warp per token, 4 outputs per lane.
// lane: row = lane>>1 (n1*4+n2), q = lane&1 (n3 in [4q,4q+4)).
// G row 64B -> 4x LDG.64-pair loads via 4 ulonglong2 (2x LDG.128 x2);
// u64 r2-pairs feed FFMA2 directly (no broadcast MOVs).
// C instr (rp,h): 16B at i3*512 + rp*64 + q*32 + h*16 -> per warp 2 distinct
// addrs inside ONE 128B line -> 1 wavefront per instruction.
// ---------------------------------------------------------------------------
__global__ void __launch_bounds__(256, 7) tt_gather(
    const void*  __restrict__ xraw,
    float*       __restrict__ out,
    int n_tok)
{
    const int t    = threadIdx.x;
    const int lane = t & 31;
    const int tok  = blockIdx.x * 8 + (t >> 5);
    if (tok >= n_tok) return;

    // --- index dtype autodetect (int64 declared, but jax may emit int32) ---
    const unsigned long long* p64 = (const unsigned long long*)xraw;
    bool is64 = true;
    #pragma unroll
    for (int j = 0; j < 4; j++)
        if (p64[j] >= VOC_LL) is64 = false;

    const long long idxll = is64 ? ((const long long*)xraw)[tok]
                                 : (long long)((const int*)xraw)[tok];
    const unsigned int iv  = (unsigned int)idxll;      // < 1e6
    const unsigned int i3  = iv % 100u;
    const unsigned int i12 = iv / 100u;

    const int row = lane >> 1;   // n1*4 + n2
    const int q   = lane & 1;    // n3 in [4q, 4q+4)

    // G row (64B): 2x LDG.128 -> 8 u64 r2-pairs
    const ulonglong2* G =
        (const ulonglong2*)(g_G01 + (size_t)i12 * 256 + row * 16);
    const ulonglong2 G0 = G[0];   // pairs (r2 0,1), (2,3)
    const ulonglong2 G1 = G[1];   // pairs (4,5), (6,7)
    const ulonglong2 G2 = G[2];   // pairs (8,9), (10,11)
    const ulonglong2 G3 = G[3];   // pairs (12,13), (14,15)

    // C base for this (i3, q): 16B chunks at rp*64 + h*16
    const char* cb = (const char*)g_C2Q + (size_t)i3 * 512 + q * 32;

    unsigned long long a0 = 0, a1 = 0, a2 = 0, a3 = 0;
    #pragma unroll
    for (int rp = 0; rp < 8; rp++) {
        const ulonglong2 c0 = *(const ulonglong2*)(cb + rp * 64);        // n3 4q,4q+1
        const ulonglong2 c1 = *(const ulonglong2*)(cb + rp * 64 + 16);   // n3 4q+2,4q+3
        unsigned long long g;
        switch (rp) {
            case 0: g = G0.x; break;  case 1: g = G0.y; break;
            case 2: g = G1.x; break;  case 3: g = G1.y; break;
            case 4: g = G2.x; break;  case 5: g = G2.y; break;
            case 6: g = G3.x; break;  default: g = G3.y; break;
        }
        a0 = f32x2_fma(g, c0.x, a0);
        a1 = f32x2_fma(g, c0.y, a1);
        a2 = f32x2_fma(g, c1.x, a2);
        a3 = f32x2_fma(g, c1.y, a3);
    }

    // horizontal add of (even,odd) r2 halves; n3 = 4q + j
    float4 res;
    res.x = f32x2_hadd(a0);
    res.y = f32x2_hadd(a1);
    res.z = f32x2_hadd(a2);
    res.w = f32x2_hadd(a3);
    if (iv == 0) { res.x = 0.f; res.y = 0.f; res.z = 0.f; res.w = 0.f; }

    *(float4*)(out + (size_t)tok * 128 + row * 8 + q * 4) = res;
}

// ---------------------------------------------------------------------------
extern "C" void kernel_launch(void* const* d_in, const int* in_sizes, int n_in,
                              void* d_out, int out_size)
{
    const void*  x     = d_in[0];
    const float* core0 = (const float*)d_in[1];
    const float* core1 = (const float*)d_in[2];
    const float* core2 = (const float*)d_in[3];
    float*       out   = (float*)d_out;

    const int n_tok = in_sizes[0];   // 32768

    tt_precompute_g01<<<dim3(100, 20), 128>>>(core0, core1);
    tt_pack_c2<<<50, 256>>>(core2);
    tt_gather<<<(n_tok + 7) / 8, 256>>>(x, out, n_tok);
}

// round 7
// speedup vs baseline: 1.3034x; 1.3034x over previous
#include <cuda_runtime.h>
#include <cstdint>

// ---------------------------------------------------------------------------
// TT embedding:  VOC = 100^3,  EMB = 4*4*8 = 128,  RANK = 16
//   out[tok, n1*32+n2*8+n3] = sum_{r1,r2} core0[i1,n1,r1]*core1[r1,i2,n2,r2]*core2[r2,i3,n3]
// idx = i1*10000 + i2*100 + i3; idx==0 (PAD) -> zero row.
//
// Kernel 1 : G01[i12][row*16+r2] = sum_r1 core0*core1  (10.2MB, L2-resident)
//            + fused pack of core2 into C2P[i3][j][q][n3] (51KB, L1-resident)
//            where r2 = 8q + j  (j in [0,8), q in {0,1}).
// Kernel 2 : warp/token. Lane (row,q) loads ONLY its r2-half of the G row
//            (2x coalesced LDG.128, zero duplication -> 16 wf vs 32),
//            C2P layout puts both q-halves in the same 128B line (16 wf),
//            partial sums merged with ONE end-of-chain butterfly.
// ---------------------------------------------------------------------------

#define VOC_LL 1000000ULL

__device__ float g_G01[10000 * 256];
__device__ float g_C2P[100 * 128];   // [i3][j][q][n3] = core2[8q+j][i3][n3]

// ---- packed fp32x2 helpers (sm_103a) --------------------------------------
__device__ __forceinline__ unsigned long long f32x2_fma(
    unsigned long long a, unsigned long long b, unsigned long long c)
{
    unsigned long long d;
    asm("fma.rn.f32x2 %0, %1, %2, %3;" : "=l"(d) : "l"(a), "l"(b), "l"(c));
    return d;
}
__device__ __forceinline__ unsigned long long f32x2_add(
    unsigned long long a, unsigned long long b)
{
    unsigned long long d;
    asm("add.rn.f32x2 %0, %1, %2;" : "=l"(d) : "l"(a), "l"(b));
    return d;
}
__device__ __forceinline__ unsigned long long f32x2_bcast(float x)
{
    unsigned long long d;
    asm("mov.b64 %0, {%1, %1};" : "=l"(d) : "f"(x));
    return d;
}
__device__ __forceinline__ unsigned long long shfl_xor_u64(unsigned long long v, int m)
{
    unsigned int lo = (unsigned int)v, hi = (unsigned int)(v >> 32);
    lo = __shfl_xor_sync(0xffffffffu, lo, m);
    hi = __shfl_xor_sync(0xffffffffu, hi, m);
    return ((unsigned long long)hi << 32) | lo;
}

// ---------------------------------------------------------------------------
// Kernel 1: G01 precompute + fused core2 pack.
// grid = (100, 21), block = 128.
//   y < 20 : G01 for i2 = blockIdx.x, i1 in [5y, 5y+5)
//   y == 20: pack core2 for i3 = blockIdx.x
// core0: (1,100,4,16)  elem (i1,n1,r1)    @ i1*64 + n1*16 + r1
// core1: (16,100,4,16) elem (r1,i2,n2,r2) @ r1*6400 + i2*64 + n2*16 + r2
// core2: (16,100,8)    elem (r2,i3,n3)    @ r2*800 + i3*8 + n3
// ---------------------------------------------------------------------------
__global__ void __launch_bounds__(128) tt_precompute(
    const float* __restrict__ core0,
    const float* __restrict__ core1,
    const float* __restrict__ core2)
{
    const int i2 = blockIdx.x;
    const int g  = blockIdx.y;
    const int p  = threadIdx.x;

    if (g == 20) {
        // pack: C2P[i3*128 + p],  p = j*16 + q*8 + n3
        const int i3 = i2;
        const int j  = p >> 4;
        const int q  = (p >> 3) & 1;
        const int n3 = p & 7;
        g_C2P[i3 * 128 + p] = core2[(8 * q + j) * 800 + i3 * 8 + n3];
        return;
    }

    __shared__ float Bs[1024];   // core1 slice for this i2: [r1][n2*16+r2]
    __shared__ float As[320];    // core0 slices for 5 i1: [q][n1*16+r1]

    #pragma unroll
    for (int j = p; j < 1024; j += 128)
        Bs[j] = core1[(j >> 6) * 6400 + i2 * 64 + (j & 63)];
    #pragma unroll
    for (int j = p; j < 320; j += 128)
        As[j] = core0[g * 320 + j];
    __syncthreads();

    const int n1 = p >> 5;         // constant per warp -> As broadcast
    const int rp = (p & 31) * 2;   // rest pair start (n2*16+r2)

    unsigned long long b2[16];
    #pragma unroll
    for (int r1 = 0; r1 < 16; r1++)
        b2[r1] = *(const unsigned long long*)&Bs[r1 * 64 + rp];

    #pragma unroll
    for (int q = 0; q < 5; q++) {
        unsigned long long acc = 0;
        #pragma unroll
        for (int r1 = 0; r1 < 16; r1++)
            acc = f32x2_fma(f32x2_bcast(As[q * 64 + n1 * 16 + r1]), b2[r1], acc);
        const int i1 = g * 5 + q;
        *(unsigned long long*)&g_G01[((size_t)(i1 * 100 + i2)) * 256 + p * 2] = acc;
    }
}

// ---------------------------------------------------------------------------
// Kernel 2: gather.  1 warp per token, 4 outputs/lane.
// lane: row = lane>>1 (n1*4+n2), q = lane&1 (r2-half owned & n3-half kept).
// G: lane loads granules 2*lane, 2*lane+1 (fully coalesced, no duplication)
//    = gr[r2] for r2 in [8q, 8q+8) of its row.
// C: for j in [0,8): 2x LDG.128 at i3*512 + j*64 + q*32 + {0,16}
//    -> warp touches ONE 128B line per instruction.
// Lane accumulates partials for all 8 n3 over its 8 r2's; one butterfly
// (lane^1) merges the halves; lane stores n3 in [4q, 4q+4).
// ---------------------------------------------------------------------------
__global__ void __launch_bounds__(256, 6) tt_gather(
    const void*  __restrict__ xraw,
    float*       __restrict__ out,
    int n_tok)
{
    const int t    = threadIdx.x;
    const int lane = t & 31;
    const int tok  = blockIdx.x * 8 + (t >> 5);
    if (tok >= n_tok) return;

    // --- index dtype autodetect (int64 declared, but jax may emit int32) ---
    const unsigned long long* p64 = (const unsigned long long*)xraw;
    bool is64 = true;
    #pragma unroll
    for (int j = 0; j < 4; j++)
        if (p64[j] >= VOC_LL) is64 = false;

    const long long idxll = is64 ? ((const long long*)xraw)[tok]
                                 : (long long)((const int*)xraw)[tok];
    const unsigned int iv  = (unsigned int)idxll;      // < 1e6
    const unsigned int i3  = iv % 100u;
    const unsigned int i12 = iv / 100u;

    const int q = lane & 1;

    // own r2-half of the G row (coalesced: granules 2*lane, 2*lane+1)
    const float4* G = (const float4*)(g_G01 + (size_t)i12 * 256);
    const float4 ga = G[2 * lane];       // r2 = 8q+0..3
    const float4 gb = G[2 * lane + 1];   // r2 = 8q+4..7
    const float gr[8] = { ga.x, ga.y, ga.z, ga.w,  gb.x, gb.y, gb.z, gb.w };

    // C2P base for (i3, q)
    const char* cb = (const char*)g_C2P + (size_t)i3 * 512 + q * 32;

    // partials for all 8 n3: acc0=(n3 0,1) acc1=(2,3) acc2=(4,5) acc3=(6,7)
    unsigned long long acc0 = 0, acc1 = 0, acc2 = 0, acc3 = 0;
    #pragma unroll
    for (int j = 0; j < 8; j++) {
        const ulonglong2 c0 = *(const ulonglong2*)(cb + j * 64);        // n3 0..3
        const ulonglong2 c1 = *(const ulonglong2*)(cb + j * 64 + 16);   // n3 4..7
        const unsigned long long gg = f32x2_bcast(gr[j]);
        acc0 = f32x2_fma(gg, c0.x, acc0);
        acc1 = f32x2_fma(gg, c0.y, acc1);
        acc2 = f32x2_fma(gg, c1.x, acc2);
        acc3 = f32x2_fma(gg, c1.y, acc3);
    }

    // single butterfly: keep n3 [4q,4q+4), exchange the other half
    const unsigned long long keep0 = q ? acc2 : acc0;
    const unsigned long long keep1 = q ? acc3 : acc1;
    const unsigned long long send0 = q ? acc0 : acc2;
    const unsigned long long send1 = q ? acc1 : acc3;
    const unsigned long long recv0 = shfl_xor_u64(send0, 1);
    const unsigned long long recv1 = shfl_xor_u64(send1, 1);

    ulonglong2 res;
    res.x = f32x2_add(keep0, recv0);
    res.y = f32x2_add(keep1, recv1);
    if (iv == 0) { res.x = 0; res.y = 0; }   // PAD row

    const int row = lane >> 1;
    *(ulonglong2*)(out + (size_t)tok * 128 + row * 8 + q * 4) = res;
}

// ---------------------------------------------------------------------------
extern "C" void kernel_launch(void* const* d_in, const int* in_sizes, int n_in,
                              void* d_out, int out_size)
{
    const void*  x     = d_in[0];
    const float* core0 = (const float*)d_in[1];
    const float* core1 = (const float*)d_in[2];
    const float* core2 = (const float*)d_in[3];
    float*       out   = (float*)d_out;

    const int n_tok = in_sizes[0];   // 32768

    tt_precompute<<<dim3(100, 21), 128>>>(core0, core1, core2);
    tt_gather<<<(n_tok + 7) / 8, 256>>>(x, out, n_tok);
}